// round 14
// baseline (speedup 1.0000x reference)
#include <cuda_runtime.h>
#include <cuda_bf16.h>
#include <math.h>
#include <stdint.h>

#define NN   8192
#define DIN  256
#define DH   128
#define DO   64
#define CAP  1024

// ---------------- scratch ----------------
__device__ float g_Wh1[(size_t)NN * DH];
__device__ float g_h1 [(size_t)NN * DH];
__device__ float g_Wh2[(size_t)NN * DO];
__device__ float g_f1a[NN], g_f2a[NN];
__device__ float g_f1b[NN], g_f2b[NN];
__device__ int   g_nbr[(size_t)NN * CAP];
__device__ float g_attv[(size_t)NN * CAP];   // normalized att values (sparse)
__device__ int   g_cnt[NN];
__device__ float g_cs1[DH], g_cs2[DO];
__device__ int   g_key1, g_key2;
__device__ __nv_bfloat16 g_h2hi[(size_t)NN * DO];
__device__ __nv_bfloat16 g_h2lo[(size_t)NN * DO];

__device__ __forceinline__ int   fenc(float f){ int k=__float_as_int(f); return k<0 ? (k^0x7FFFFFFF) : k; }
__device__ __forceinline__ float fdec(int k){ return __int_as_float(k<0 ? (k^0x7FFFFFFF) : k); }

// fast sigmoid: 1 MUFU (tanh.approx) + 1 MUL + 1 FFMA, no divide
__device__ __forceinline__ float sigf(float x){
    float t;
    asm("tanh.approx.f32 %0, %1;" : "=f"(t) : "f"(0.5f * x));
    return fmaf(0.5f, t, 0.5f);
}

// ---------------- init ----------------
__global__ void k_init() {
    int t = threadIdx.x;
    if (t < DH) g_cs1[t] = 0.f;
    if (t < DO) g_cs2[t] = 0.f;
    if (t == 0) { g_key1 = 0x80000000; g_key2 = 0x80000000; }
}

// ---------------- layer1 projection: Wh1 = X @ W1 (8 rows/block, 2 cols/thread) ----------------
__global__ __launch_bounds__(64) void k_wh1(const float* __restrict__ X,
                                            const float* __restrict__ W1) {
    __shared__ float Xs[8][DIN];
    int r0 = blockIdx.x * 8, tid = threadIdx.x;
    const float4* xp = (const float4*)(X + (size_t)r0 * DIN);
    float4* sp = (float4*)&Xs[0][0];
    for (int i = tid; i < 8 * DIN / 4; i += 64) sp[i] = xp[i];
    __syncthreads();
    float a0[8], a1r[8];
#pragma unroll
    for (int r = 0; r < 8; r++) { a0[r] = 0.f; a1r[r] = 0.f; }
#pragma unroll 2
    for (int t = 0; t < DIN; t++) {
        float w0 = W1[t * DH + tid];
        float w1 = W1[t * DH + tid + 64];
#pragma unroll
        for (int r = 0; r < 8; r++) {
            float x = Xs[r][t];
            a0[r]  = fmaf(x, w0, a0[r]);
            a1r[r] = fmaf(x, w1, a1r[r]);
        }
    }
#pragma unroll
    for (int r = 0; r < 8; r++) {
        g_Wh1[(size_t)(r0 + r) * DH + tid]      = a0[r];
        g_Wh1[(size_t)(r0 + r) * DH + tid + 64] = a1r[r];
    }
}

// ---------------- f1/f2 + global max (layer1): warp per row ----------------
__global__ __launch_bounds__(256) void k_feat1(const float* __restrict__ a1) {
    int w = threadIdx.x >> 5, l = threadIdx.x & 31;
    int row = blockIdx.x * 8 + w;
    float4 v = *(const float4*)&g_Wh1[(size_t)row * DH + l * 4];
    float4 p = *(const float4*)&a1[l * 4];
    float4 q = *(const float4*)&a1[DH + l * 4];
    float s1 = v.x * p.x + v.y * p.y + v.z * p.z + v.w * p.w;
    float s2 = v.x * q.x + v.y * q.y + v.z * q.z + v.w * q.w;
#pragma unroll
    for (int o = 16; o; o >>= 1) {
        s1 += __shfl_xor_sync(0xFFFFFFFFu, s1, o);
        s2 += __shfl_xor_sync(0xFFFFFFFFu, s2, o);
    }
    if (l == 0) { g_f1a[row] = s1; g_f2a[row] = s2; atomicMax(&g_key1, fenc(s2)); }
}

// ---------------- column sums (empty-row fallback) ----------------
__global__ void k_cs1() {
    int k = threadIdx.x; int r0 = blockIdx.x * 128;
    float s = 0.f;
    for (int r = r0; r < r0 + 128; r++) s += g_Wh1[(size_t)r * DH + k];
    atomicAdd(&g_cs1[k], s);
}
__global__ void k_cs2() {
    int k = threadIdx.x; int r0 = blockIdx.x * 128;
    float s = 0.f;
    for (int r = r0; r < r0 + 128; r++) s += g_Wh2[(size_t)r * DO + k];
    atomicAdd(&g_cs2[k], s);
}

// ---------------- layer1 fused: adj scan -> nbr list + sparse att values, hp1, elu ----------------
// Dense att materialization deferred to k_att_store (overlapped stream).
__global__ __launch_bounds__(256) void k_att1(const float* __restrict__ adj) {
    __shared__ int   s_idx[CAP];
    __shared__ float s_p[CAP];
    __shared__ float s_red[256];
    __shared__ int   s_cnt;
    int row = blockIdx.x, tid = threadIdx.x;
    if (tid == 0) s_cnt = 0;
    __syncthreads();

    float f1 = g_f1a[row];
    float mm = f1 + fdec(g_key1);
    float c = mm > 0.f ? mm : 0.2f * mm;

    const float4* arow = (const float4*)(adj + (size_t)row * NN);
    for (int v = tid; v < NN / 4; v += 256) {
        float4 a = arow[v];
        if (a.x > 0.f) { int j = 4*v + 0; float e = f1 + g_f2a[j]; e = e > 0.f ? e : 0.2f * e;
                         int p = atomicAdd(&s_cnt, 1); if (p < CAP) { s_idx[p] = j; s_p[p] = __expf(e - c); } }
        if (a.y > 0.f) { int j = 4*v + 1; float e = f1 + g_f2a[j]; e = e > 0.f ? e : 0.2f * e;
                         int p = atomicAdd(&s_cnt, 1); if (p < CAP) { s_idx[p] = j; s_p[p] = __expf(e - c); } }
        if (a.z > 0.f) { int j = 4*v + 2; float e = f1 + g_f2a[j]; e = e > 0.f ? e : 0.2f * e;
                         int p = atomicAdd(&s_cnt, 1); if (p < CAP) { s_idx[p] = j; s_p[p] = __expf(e - c); } }
        if (a.w > 0.f) { int j = 4*v + 3; float e = f1 + g_f2a[j]; e = e > 0.f ? e : 0.2f * e;
                         int p = atomicAdd(&s_cnt, 1); if (p < CAP) { s_idx[p] = j; s_p[p] = __expf(e - c); } }
    }
    __syncthreads();
    int cnt = min(s_cnt, CAP);
    if (tid == 0) g_cnt[row] = cnt;

    float ps = 0.f;
    for (int t = tid; t < cnt; t += 256) ps += s_p[t];
    s_red[tid] = ps; __syncthreads();
    for (int s = 128; s > 0; s >>= 1) { if (tid < s) s_red[tid] += s_red[tid + s]; __syncthreads(); }
    float ssum = s_red[0];

    if (cnt == 0) {
        if (tid < DH) {
            float hp = g_cs1[tid] * (1.0f / NN);
            g_h1[(size_t)row * DH + tid] = hp > 0.f ? hp : expm1f(hp);
        }
        return;
    }
    float inv = 1.f / ssum;
    for (int t = tid; t < cnt; t += 256) {
        g_nbr [(size_t)row * CAP + t] = s_idx[t];
        g_attv[(size_t)row * CAP + t] = s_p[t] * inv;
    }

    int k = tid & 127, half = tid >> 7;
    float acc = 0.f;
    for (int t = half; t < cnt; t += 2)
        acc += s_p[t] * g_Wh1[(size_t)s_idx[t] * DH + k];
    __syncthreads();
    s_red[tid] = acc; __syncthreads();
    if (half == 0) {
        float hp = (s_red[k] + s_red[k + 128]) * inv;
        g_h1[(size_t)row * DH + k] = hp > 0.f ? hp : expm1f(hp);
    }
}

// ---------------- dense att materialization (runs on overlap stream) ----------------
__global__ __launch_bounds__(256) void k_att_store(float* __restrict__ att) {
    int row = blockIdx.x, tid = threadIdx.x;
    int cnt = g_cnt[row];
    float4* orow = (float4*)(att + (size_t)row * NN);
    if (cnt == 0) {
        float4 u = make_float4(1.0f/NN, 1.0f/NN, 1.0f/NN, 1.0f/NN);
        for (int v = tid; v < NN / 4; v += 256) orow[v] = u;
        return;
    }
    float4 z = make_float4(0.f, 0.f, 0.f, 0.f);
    for (int v = tid; v < NN / 4; v += 256) orow[v] = z;
    __syncthreads();
    for (int t = tid; t < cnt; t += 256)
        att[(size_t)row * NN + g_nbr[(size_t)row * CAP + t]] = g_attv[(size_t)row * CAP + t];
}

// ---------------- layer2 projection ----------------
__global__ __launch_bounds__(32) void k_wh2(const float* __restrict__ W2) {
    __shared__ float Xs[8][DH];
    int r0 = blockIdx.x * 8, tid = threadIdx.x;
    const float4* xp = (const float4*)(g_h1 + (size_t)r0 * DH);
    float4* sp = (float4*)&Xs[0][0];
    for (int i = tid; i < 8 * DH / 4; i += 32) sp[i] = xp[i];
    __syncthreads();
    float a0[8], a1r[8];
#pragma unroll
    for (int r = 0; r < 8; r++) { a0[r] = 0.f; a1r[r] = 0.f; }
#pragma unroll 2
    for (int t = 0; t < DH; t++) {
        float w0 = W2[t * DO + tid];
        float w1 = W2[t * DO + tid + 32];
#pragma unroll
        for (int r = 0; r < 8; r++) {
            float x = Xs[r][t];
            a0[r]  = fmaf(x, w0, a0[r]);
            a1r[r] = fmaf(x, w1, a1r[r]);
        }
    }
#pragma unroll
    for (int r = 0; r < 8; r++) {
        g_Wh2[(size_t)(r0 + r) * DO + tid]      = a0[r];
        g_Wh2[(size_t)(r0 + r) * DO + tid + 32] = a1r[r];
    }
}

// ---------------- f1/f2 + global max (layer2) ----------------
__global__ __launch_bounds__(256) void k_feat2(const float* __restrict__ a2) {
    int w = threadIdx.x >> 5, l = threadIdx.x & 31;
    int row = blockIdx.x * 8 + w;
    float2 v = *(const float2*)&g_Wh2[(size_t)row * DO + l * 2];
    float2 p = *(const float2*)&a2[l * 2];
    float2 q = *(const float2*)&a2[DO + l * 2];
    float s1 = v.x * p.x + v.y * p.y;
    float s2 = v.x * q.x + v.y * q.y;
#pragma unroll
    for (int o = 16; o; o >>= 1) {
        s1 += __shfl_xor_sync(0xFFFFFFFFu, s1, o);
        s2 += __shfl_xor_sync(0xFFFFFFFFu, s2, o);
    }
    if (l == 0) { g_f1b[row] = s1; g_f2b[row] = s2; atomicMax(&g_key2, fenc(s2)); }
}

// ---------------- layer2 fused ----------------
__global__ __launch_bounds__(128) void k_att2(float* __restrict__ h2) {
    __shared__ int   s_idx[CAP];
    __shared__ float s_p[CAP];
    __shared__ float s_red[128];
    int row = blockIdx.x, tid = threadIdx.x;
    int cnt = g_cnt[row];
    float f1 = g_f1b[row];
    float mm = f1 + fdec(g_key2);
    float c = mm > 0.f ? mm : 0.2f * mm;

    float ps = 0.f;
    for (int t = tid; t < cnt; t += 128) {
        int j = g_nbr[(size_t)row * CAP + t];
        float e = f1 + g_f2b[j]; e = e > 0.f ? e : 0.2f * e;
        float p = __expf(e - c);
        s_idx[t] = j; s_p[t] = p; ps += p;
    }
    s_red[tid] = ps; __syncthreads();
    for (int s = 64; s > 0; s >>= 1) { if (tid < s) s_red[tid] += s_red[tid + s]; __syncthreads(); }
    float ssum = s_red[0];

    if (cnt == 0) {
        if (tid < DO) h2[(size_t)row * DO + tid] = g_cs2[tid] * (1.0f / NN);
        return;
    }
    float inv = 1.f / ssum;
    int k = tid & 63, half = tid >> 6;
    float acc = 0.f;
    for (int t = half; t < cnt; t += 2)
        acc += s_p[t] * g_Wh2[(size_t)s_idx[t] * DO + k];
    __syncthreads();
    s_red[tid] = acc; __syncthreads();
    if (half == 0)
        h2[(size_t)row * DO + k] = (s_red[k] + s_red[k + 64]) * inv;
}

// ---------------- split h2 into bf16 hi/lo ----------------
__global__ __launch_bounds__(256) void k_split(const float* __restrict__ h2) {
    int i = blockIdx.x * 256 + threadIdx.x;
    float x = h2[i];
    __nv_bfloat16 hi = __float2bfloat16(x);
    float r = x - __bfloat162float(hi);
    g_h2hi[i] = hi;
    g_h2lo[i] = __float2bfloat16(r);
}

// ---------------- decoder: mma.sync bf16-split GEMM + symmetry mirror ----------------
__device__ __forceinline__ uint32_t swz_off(int row, int ch){
    return (uint32_t)(row * 256 + ((ch ^ (row & 7)) << 4));
}
__device__ __forceinline__ void ldsm4(uint32_t* r, uint32_t addr){
    asm volatile("ldmatrix.sync.aligned.m8n8.x4.shared.b16 {%0,%1,%2,%3}, [%4];"
                 : "=r"(r[0]), "=r"(r[1]), "=r"(r[2]), "=r"(r[3]) : "r"(addr));
}
__device__ __forceinline__ void mma16816(float* d, const uint32_t* a, uint32_t b0, uint32_t b1){
    asm volatile("mma.sync.aligned.m16n8k16.row.col.f32.bf16.bf16.f32 "
                 "{%0,%1,%2,%3}, {%4,%5,%6,%7}, {%8,%9}, {%0,%1,%2,%3};"
                 : "+f"(d[0]), "+f"(d[1]), "+f"(d[2]), "+f"(d[3])
                 : "r"(a[0]), "r"(a[1]), "r"(a[2]), "r"(a[3]), "r"(b0), "r"(b1));
}

__global__ __launch_bounds__(256) void k_dec(float* __restrict__ G) {
    if (blockIdx.x < blockIdx.y) return;   // symmetry: upper-triangular tiles only
    extern __shared__ char sm[];
    char* sA = sm;
    char* sB = sm + 32768;
    uint32_t sAu, sBu;
    asm("{ .reg .u64 t; cvta.to.shared.u64 t, %1; cvt.u32.u64 %0, t; }" : "=r"(sAu) : "l"(sA));
    asm("{ .reg .u64 t; cvta.to.shared.u64 t, %1; cvt.u32.u64 %0, t; }" : "=r"(sBu) : "l"(sB));

    int tid = threadIdx.x;
    int wid = tid >> 5, l = tid & 31;
    int wm = wid >> 1, wn = wid & 1;
    int M0 = blockIdx.y * 128, N0 = blockIdx.x * 128;

    const uint4* hi = (const uint4*)g_h2hi;
    const uint4* lo = (const uint4*)g_h2lo;
    for (int i = tid; i < 2048; i += 256) {
        int r = i >> 4, ch = i & 15, c8 = ch & 7;
        const uint4* src = (ch < 8) ? hi : lo;
        *(uint4*)(sA + swz_off(r, ch)) = src[(size_t)(M0 + r) * 8 + c8];
        *(uint4*)(sB + swz_off(r, ch)) = src[(size_t)(N0 + r) * 8 + c8];
    }
    __syncthreads();

    float acc[2][8][4];
#pragma unroll
    for (int mt = 0; mt < 2; mt++)
#pragma unroll
        for (int nt = 0; nt < 8; nt++)
#pragma unroll
            for (int q = 0; q < 4; q++) acc[mt][nt][q] = 0.f;

    const int KA[12] = {0,16,32,48,  0,16,32,48,  64,80,96,112};
    const int KB[12] = {0,16,32,48,  64,80,96,112, 0,16,32,48};

    int sel = l >> 3, rin = l & 7;
#pragma unroll 1
    for (int s = 0; s < 12; s++) {
        int ka = KA[s], kb = KB[s];
        uint32_t a[2][4];
#pragma unroll
        for (int mt = 0; mt < 2; mt++) {
            int row = wm * 32 + mt * 16 + (sel & 1) * 8 + rin;
            int ch  = (ka >> 3) + (sel >> 1);
            ldsm4(a[mt], sAu + swz_off(row, ch));
        }
        uint32_t b[4][4];
#pragma unroll
        for (int p = 0; p < 4; p++) {
            int row = wn * 64 + p * 16 + (sel >> 1) * 8 + rin;
            int ch  = (kb >> 3) + (sel & 1);
            ldsm4(b[p], sBu + swz_off(row, ch));
        }
#pragma unroll
        for (int mt = 0; mt < 2; mt++)
#pragma unroll
            for (int nt = 0; nt < 8; nt++) {
                int p = nt >> 1, h = (nt & 1) * 2;
                mma16816(acc[mt][nt], a[mt], b[p][h], b[p][h + 1]);
            }
    }

    bool diag = (blockIdx.x == blockIdx.y);
    float* s_t = (float*)sm;
    __syncthreads();

#pragma unroll
    for (int mt = 0; mt < 2; mt++)
#pragma unroll
        for (int h = 0; h < 2; h++) {
            int ml = wm * 32 + mt * 16 + h * 8 + (l >> 2);
            int m = M0 + ml;
            float maskm = g_cnt[m] > 0 ? 1.f : 0.f;
            float* gp = G + (size_t)m * NN + N0 + wn * 64 + 2 * (l & 3);
            int nbase = wn * 64 + 2 * (l & 3);
#pragma unroll
            for (int nt = 0; nt < 8; nt++) {
                float s0  = sigf(acc[mt][nt][h * 2 + 0]);
                float s1v = sigf(acc[mt][nt][h * 2 + 1]);
                int nl = nbase + nt * 8;
                if (!diag) {
                    s_t[ml * 128 + ((nl)     ^ (ml & 31))] = s0;
                    s_t[ml * 128 + ((nl + 1) ^ (ml & 31))] = s1v;
                }
                float2 o; o.x = maskm * s0; o.y = maskm * s1v;
                *(float2*)(gp + nt * 8) = o;
            }
        }

    if (diag) return;
    __syncthreads();

    for (int i = tid; i < 128 * 128; i += 256) {
        int nl = i >> 7, ml = i & 127;
        int n = N0 + nl;
        float maskn = g_cnt[n] > 0 ? 1.f : 0.f;
        float v = s_t[ml * 128 + (nl ^ (ml & 31))];
        G[(size_t)n * NN + M0 + ml] = maskn * v;
    }
}

// ---------------- launch ----------------
extern "C" void kernel_launch(void* const* d_in, const int* in_sizes, int n_in,
                              void* d_out, int out_size) {
    const float* X   = (const float*)d_in[0];
    const float* adj = (const float*)d_in[1];
    const float* W1  = (const float*)d_in[2];
    const float* a1  = (const float*)d_in[3];
    const float* W2  = (const float*)d_in[4];
    const float* a2  = (const float*)d_in[5];

    float* out = (float*)d_out;
    float* h2  = out;                                  // [NN, DO]
    float* gen = out + (size_t)NN * DO;                // [NN, NN]
    float* att = gen + (size_t)NN * NN;                // [NN, NN]

    static cudaStream_t s2 = nullptr;
    static cudaEvent_t evA = nullptr, evB = nullptr;
    static int inited = 0;
    if (!inited) {
        cudaStreamCreateWithFlags(&s2, cudaStreamNonBlocking);
        cudaEventCreateWithFlags(&evA, cudaEventDisableTiming);
        cudaEventCreateWithFlags(&evB, cudaEventDisableTiming);
        cudaFuncSetAttribute(k_dec, cudaFuncAttributeMaxDynamicSharedMemorySize, 65536);
        inited = 1;
    }

    k_init<<<1, 128>>>();
    k_wh1<<<NN / 8, 64>>>(X, W1);
    k_cs1<<<64, 128>>>();
    k_feat1<<<NN / 8, 256>>>(a1);
    k_att1<<<NN, 256>>>(adj);

    // fork: dense att materialization overlaps the rest of the pipeline
    cudaEventRecord(evA, 0);
    cudaStreamWaitEvent(s2, evA, 0);
    k_att_store<<<NN, 256, 0, s2>>>(att);
    cudaEventRecord(evB, s2);

    k_wh2<<<NN / 8, 32>>>(W2);
    k_cs2<<<64, 64>>>();
    k_feat2<<<NN / 8, 256>>>(a2);
    k_att2<<<NN, 128>>>(h2);
    k_split<<<NN * DO / 256, 256>>>(h2);

    dim3 gdim(NN / 128, NN / 128);
    k_dec<<<gdim, 256, 65536>>>(gen);

    cudaStreamWaitEvent(0, evB, 0);   // join forked branch before graph end
}

// round 17
// speedup vs baseline: 1.1430x; 1.1430x over previous
#include <cuda_runtime.h>
#include <cuda_bf16.h>
#include <math.h>
#include <stdint.h>

#define NN   8192
#define DIN  256
#define DH   128
#define DO   64
#define CAP  1024

// ---------------- scratch ----------------
__device__ float g_Wh1[(size_t)NN * DH];
__device__ float g_h1 [(size_t)NN * DH];
__device__ float g_Wh2[(size_t)NN * DO];
__device__ float g_f1a[NN], g_f2a[NN];
__device__ float g_f1b[NN], g_f2b[NN];
__device__ int   g_nbr[(size_t)NN * CAP];
__device__ int   g_cnt[NN];
__device__ float g_cs1[DH], g_cs2[DO];
__device__ int   g_key1, g_key2;
__device__ __nv_bfloat16 g_h2hi[(size_t)NN * DO];
__device__ __nv_bfloat16 g_h2lo[(size_t)NN * DO];

__device__ __forceinline__ int   fenc(float f){ int k=__float_as_int(f); return k<0 ? (k^0x7FFFFFFF) : k; }
__device__ __forceinline__ float fdec(int k){ return __int_as_float(k<0 ? (k^0x7FFFFFFF) : k); }

// fast sigmoid: 1 MUFU (tanh.approx) + 1 MUL + 1 FFMA, no divide
__device__ __forceinline__ float sigf(float x){
    float t;
    asm("tanh.approx.f32 %0, %1;" : "=f"(t) : "f"(0.5f * x));
    return fmaf(0.5f, t, 0.5f);
}

// ---------------- init ----------------
__global__ void k_init() {
    int t = threadIdx.x;
    if (t < DH) g_cs1[t] = 0.f;
    if (t < DO) g_cs2[t] = 0.f;
    if (t == 0) { g_key1 = 0x80000000; g_key2 = 0x80000000; }
}

// ---------------- layer1 projection FUSED: Wh1 = X @ W1, col-sums, f1/f2 + max ----------------
__global__ __launch_bounds__(64) void k_wh1(const float* __restrict__ X,
                                            const float* __restrict__ W1,
                                            const float* __restrict__ a1) {
    __shared__ float Xs[8][DIN];
    __shared__ float rf1[8][64], rf2[8][64];
    int r0 = blockIdx.x * 8, tid = threadIdx.x;
    const float4* xp = (const float4*)(X + (size_t)r0 * DIN);
    float4* sp = (float4*)&Xs[0][0];
    for (int i = tid; i < 8 * DIN / 4; i += 64) sp[i] = xp[i];
    __syncthreads();
    float a0[8], a1r[8];
#pragma unroll
    for (int r = 0; r < 8; r++) { a0[r] = 0.f; a1r[r] = 0.f; }
#pragma unroll 2
    for (int t = 0; t < DIN; t++) {
        float w0 = W1[t * DH + tid];
        float w1 = W1[t * DH + tid + 64];
#pragma unroll
        for (int r = 0; r < 8; r++) {
            float x = Xs[r][t];
            a0[r]  = fmaf(x, w0, a0[r]);
            a1r[r] = fmaf(x, w1, a1r[r]);
        }
    }
    float v1a = a1[tid],      v1b = a1[tid + 64];
    float v2a = a1[DH + tid], v2b = a1[DH + tid + 64];
    float cs_lo = 0.f, cs_hi = 0.f;
#pragma unroll
    for (int r = 0; r < 8; r++) {
        g_Wh1[(size_t)(r0 + r) * DH + tid]      = a0[r];
        g_Wh1[(size_t)(r0 + r) * DH + tid + 64] = a1r[r];
        rf1[r][tid] = a0[r] * v1a + a1r[r] * v1b;
        rf2[r][tid] = a0[r] * v2a + a1r[r] * v2b;
        cs_lo += a0[r]; cs_hi += a1r[r];
    }
    atomicAdd(&g_cs1[tid], cs_lo);
    atomicAdd(&g_cs1[tid + 64], cs_hi);
    __syncthreads();
    if (tid < 8) {                       // f1 for row tid
        float s = 0.f;
#pragma unroll 8
        for (int c = 0; c < 64; c++) s += rf1[tid][c];
        g_f1a[r0 + tid] = s;
    } else if (tid < 16) {               // f2 for row tid-8
        int r = tid - 8;
        float s = 0.f;
#pragma unroll 8
        for (int c = 0; c < 64; c++) s += rf2[r][c];
        g_f2a[r0 + r] = s;
        atomicMax(&g_key1, fenc(s));
    }
}

// ---------------- layer1 fused: adj scan -> nbr list, dense att store, hp1, elu ----------------
__global__ __launch_bounds__(256) void k_att1(const float* __restrict__ adj,
                                              float* __restrict__ att) {
    __shared__ int   s_idx[CAP];
    __shared__ float s_p[CAP];
    __shared__ float s_red[256];
    __shared__ int   s_cnt;
    int row = blockIdx.x, tid = threadIdx.x;
    if (tid == 0) s_cnt = 0;
    __syncthreads();

    float f1 = g_f1a[row];
    float mm = f1 + fdec(g_key1);
    float c = mm > 0.f ? mm : 0.2f * mm;

    const float4* arow = (const float4*)(adj + (size_t)row * NN);
    float4*       orow = (float4*)(att + (size_t)row * NN);
    for (int v = tid; v < NN / 4; v += 256) {
        float4 a = arow[v];
        orow[v] = make_float4(0.f, 0.f, 0.f, 0.f);
        if (a.x > 0.f) { int j = 4*v + 0; float e = f1 + g_f2a[j]; e = e > 0.f ? e : 0.2f * e;
                         int p = atomicAdd(&s_cnt, 1); if (p < CAP) { s_idx[p] = j; s_p[p] = __expf(e - c); } }
        if (a.y > 0.f) { int j = 4*v + 1; float e = f1 + g_f2a[j]; e = e > 0.f ? e : 0.2f * e;
                         int p = atomicAdd(&s_cnt, 1); if (p < CAP) { s_idx[p] = j; s_p[p] = __expf(e - c); } }
        if (a.z > 0.f) { int j = 4*v + 2; float e = f1 + g_f2a[j]; e = e > 0.f ? e : 0.2f * e;
                         int p = atomicAdd(&s_cnt, 1); if (p < CAP) { s_idx[p] = j; s_p[p] = __expf(e - c); } }
        if (a.w > 0.f) { int j = 4*v + 3; float e = f1 + g_f2a[j]; e = e > 0.f ? e : 0.2f * e;
                         int p = atomicAdd(&s_cnt, 1); if (p < CAP) { s_idx[p] = j; s_p[p] = __expf(e - c); } }
    }
    __syncthreads();
    int cnt = min(s_cnt, CAP);
    if (tid == 0) g_cnt[row] = cnt;

    float ps = 0.f;
    for (int t = tid; t < cnt; t += 256) ps += s_p[t];
    s_red[tid] = ps; __syncthreads();
    for (int s = 128; s > 0; s >>= 1) { if (tid < s) s_red[tid] += s_red[tid + s]; __syncthreads(); }
    float ssum = s_red[0];

    for (int t = tid; t < cnt; t += 256) g_nbr[(size_t)row * CAP + t] = s_idx[t];

    if (cnt == 0) {
        for (int v = tid; v < NN; v += 256) att[(size_t)row * NN + v] = 1.0f / NN;
        if (tid < DH) {
            float hp = g_cs1[tid] * (1.0f / NN);
            g_h1[(size_t)row * DH + tid] = hp > 0.f ? hp : expm1f(hp);
        }
        return;
    }
    float inv = 1.f / ssum;
    for (int t = tid; t < cnt; t += 256)
        att[(size_t)row * NN + s_idx[t]] = s_p[t] * inv;

    int k = tid & 127, half = tid >> 7;
    float acc = 0.f;
    for (int t = half; t < cnt; t += 2)
        acc += s_p[t] * g_Wh1[(size_t)s_idx[t] * DH + k];
    __syncthreads();
    s_red[tid] = acc; __syncthreads();
    if (half == 0) {
        float hp = (s_red[k] + s_red[k + 128]) * inv;
        g_h1[(size_t)row * DH + k] = hp > 0.f ? hp : expm1f(hp);
    }
}

// ---------------- layer2 projection FUSED: Wh2 = h1 @ W2, col-sums, f1b/f2b + max ----------------
__global__ __launch_bounds__(32) void k_wh2(const float* __restrict__ W2,
                                            const float* __restrict__ a2) {
    __shared__ float Xs[8][DH];
    __shared__ float rf1[8][32], rf2[8][32];
    int r0 = blockIdx.x * 8, tid = threadIdx.x;
    const float4* xp = (const float4*)(g_h1 + (size_t)r0 * DH);
    float4* sp = (float4*)&Xs[0][0];
    for (int i = tid; i < 8 * DH / 4; i += 32) sp[i] = xp[i];
    __syncthreads();
    float a0[8], a1r[8];
#pragma unroll
    for (int r = 0; r < 8; r++) { a0[r] = 0.f; a1r[r] = 0.f; }
#pragma unroll 2
    for (int t = 0; t < DH; t++) {
        float w0 = W2[t * DO + tid];
        float w1 = W2[t * DO + tid + 32];
#pragma unroll
        for (int r = 0; r < 8; r++) {
            float x = Xs[r][t];
            a0[r]  = fmaf(x, w0, a0[r]);
            a1r[r] = fmaf(x, w1, a1r[r]);
        }
    }
    float v1a = a2[tid],      v1b = a2[tid + 32];
    float v2a = a2[DO + tid], v2b = a2[DO + tid + 32];
    float cs_lo = 0.f, cs_hi = 0.f;
#pragma unroll
    for (int r = 0; r < 8; r++) {
        g_Wh2[(size_t)(r0 + r) * DO + tid]      = a0[r];
        g_Wh2[(size_t)(r0 + r) * DO + tid + 32] = a1r[r];
        rf1[r][tid] = a0[r] * v1a + a1r[r] * v1b;
        rf2[r][tid] = a0[r] * v2a + a1r[r] * v2b;
        cs_lo += a0[r]; cs_hi += a1r[r];
    }
    atomicAdd(&g_cs2[tid], cs_lo);
    atomicAdd(&g_cs2[tid + 32], cs_hi);
    __syncwarp();
    if (tid < 8) {
        float s = 0.f;
#pragma unroll 8
        for (int c = 0; c < 32; c++) s += rf1[tid][c];
        g_f1b[r0 + tid] = s;
    } else if (tid < 16) {
        int r = tid - 8;
        float s = 0.f;
#pragma unroll 8
        for (int c = 0; c < 32; c++) s += rf2[r][c];
        g_f2b[r0 + r] = s;
        atomicMax(&g_key2, fenc(s));
    }
}

// ---------------- layer2 fused: softmax + h2 = att2 @ Wh2 + bf16 split ----------------
__global__ __launch_bounds__(128) void k_att2(float* __restrict__ h2) {
    __shared__ int   s_idx[CAP];
    __shared__ float s_p[CAP];
    __shared__ float s_red[128];
    int row = blockIdx.x, tid = threadIdx.x;
    int cnt = g_cnt[row];
    float f1 = g_f1b[row];
    float mm = f1 + fdec(g_key2);
    float c = mm > 0.f ? mm : 0.2f * mm;

    float ps = 0.f;
    for (int t = tid; t < cnt; t += 128) {
        int j = g_nbr[(size_t)row * CAP + t];
        float e = f1 + g_f2b[j]; e = e > 0.f ? e : 0.2f * e;
        float p = __expf(e - c);
        s_idx[t] = j; s_p[t] = p; ps += p;
    }
    s_red[tid] = ps; __syncthreads();
    for (int s = 64; s > 0; s >>= 1) { if (tid < s) s_red[tid] += s_red[tid + s]; __syncthreads(); }
    float ssum = s_red[0];

    if (cnt == 0) {
        if (tid < DO) {
            float v = g_cs2[tid] * (1.0f / NN);
            h2[(size_t)row * DO + tid] = v;
            __nv_bfloat16 hi = __float2bfloat16(v);
            g_h2hi[(size_t)row * DO + tid] = hi;
            g_h2lo[(size_t)row * DO + tid] = __float2bfloat16(v - __bfloat162float(hi));
        }
        return;
    }
    float inv = 1.f / ssum;
    int k = tid & 63, half = tid >> 6;
    float acc = 0.f;
    for (int t = half; t < cnt; t += 2)
        acc += s_p[t] * g_Wh2[(size_t)s_idx[t] * DO + k];
    __syncthreads();
    s_red[tid] = acc; __syncthreads();
    if (half == 0) {
        float v = (s_red[k] + s_red[k + 64]) * inv;
        h2[(size_t)row * DO + k] = v;
        __nv_bfloat16 hi = __float2bfloat16(v);
        g_h2hi[(size_t)row * DO + k] = hi;
        g_h2lo[(size_t)row * DO + k] = __float2bfloat16(v - __bfloat162float(hi));
    }
}

// ---------------- decoder: mma.sync bf16-split GEMM + symmetry mirror ----------------
__device__ __forceinline__ uint32_t swz_off(int row, int ch){
    return (uint32_t)(row * 256 + ((ch ^ (row & 7)) << 4));
}
__device__ __forceinline__ void ldsm4(uint32_t* r, uint32_t addr){
    asm volatile("ldmatrix.sync.aligned.m8n8.x4.shared.b16 {%0,%1,%2,%3}, [%4];"
                 : "=r"(r[0]), "=r"(r[1]), "=r"(r[2]), "=r"(r[3]) : "r"(addr));
}
__device__ __forceinline__ void mma16816(float* d, const uint32_t* a, uint32_t b0, uint32_t b1){
    asm volatile("mma.sync.aligned.m16n8k16.row.col.f32.bf16.bf16.f32 "
                 "{%0,%1,%2,%3}, {%4,%5,%6,%7}, {%8,%9}, {%0,%1,%2,%3};"
                 : "+f"(d[0]), "+f"(d[1]), "+f"(d[2]), "+f"(d[3])
                 : "r"(a[0]), "r"(a[1]), "r"(a[2]), "r"(a[3]), "r"(b0), "r"(b1));
}

__global__ __launch_bounds__(256) void k_dec(float* __restrict__ G) {
    if (blockIdx.x < blockIdx.y) return;   // symmetry: upper-triangular tiles only
    extern __shared__ char sm[];
    char* sA = sm;
    char* sB = sm + 32768;
    uint32_t sAu, sBu;
    asm("{ .reg .u64 t; cvta.to.shared.u64 t, %1; cvt.u32.u64 %0, t; }" : "=r"(sAu) : "l"(sA));
    asm("{ .reg .u64 t; cvta.to.shared.u64 t, %1; cvt.u32.u64 %0, t; }" : "=r"(sBu) : "l"(sB));

    int tid = threadIdx.x;
    int wid = tid >> 5, l = tid & 31;
    int wm = wid >> 1, wn = wid & 1;
    int M0 = blockIdx.y * 128, N0 = blockIdx.x * 128;

    const uint4* hi = (const uint4*)g_h2hi;
    const uint4* lo = (const uint4*)g_h2lo;
    for (int i = tid; i < 2048; i += 256) {
        int r = i >> 4, ch = i & 15, c8 = ch & 7;
        const uint4* src = (ch < 8) ? hi : lo;
        *(uint4*)(sA + swz_off(r, ch)) = src[(size_t)(M0 + r) * 8 + c8];
        *(uint4*)(sB + swz_off(r, ch)) = src[(size_t)(N0 + r) * 8 + c8];
    }
    __syncthreads();

    float acc[2][8][4];
#pragma unroll
    for (int mt = 0; mt < 2; mt++)
#pragma unroll
        for (int nt = 0; nt < 8; nt++)
#pragma unroll
            for (int q = 0; q < 4; q++) acc[mt][nt][q] = 0.f;

    int sel = l >> 3, rin = l & 7;
    int a_chbase = sel >> 1, b_chbase = sel & 1;

    // 4 k-chunks; per chunk load Ahi/Alo/Bhi/Blo fragments once, issue 3 MMA groups
#pragma unroll 1
    for (int kc = 0; kc < 4; kc++) {
        uint32_t ahi[2][4], alo[2][4];
#pragma unroll
        for (int mt = 0; mt < 2; mt++) {
            int row = wm * 32 + mt * 16 + (sel & 1) * 8 + rin;
            ldsm4(ahi[mt], sAu + swz_off(row, 2 * kc + a_chbase));
            ldsm4(alo[mt], sAu + swz_off(row, 8 + 2 * kc + a_chbase));
        }
        uint32_t bhi[4][4], blo[4][4];
#pragma unroll
        for (int p = 0; p < 4; p++) {
            int row = wn * 64 + p * 16 + (sel >> 1) * 8 + rin;
            ldsm4(bhi[p], sBu + swz_off(row, 2 * kc + b_chbase));
            ldsm4(blo[p], sBu + swz_off(row, 8 + 2 * kc + b_chbase));
        }
#pragma unroll
        for (int mt = 0; mt < 2; mt++)
#pragma unroll
            for (int nt = 0; nt < 8; nt++) {
                int p = nt >> 1, h = (nt & 1) * 2;
                mma16816(acc[mt][nt], ahi[mt], bhi[p][h], bhi[p][h + 1]);
                mma16816(acc[mt][nt], ahi[mt], blo[p][h], blo[p][h + 1]);
                mma16816(acc[mt][nt], alo[mt], bhi[p][h], bhi[p][h + 1]);
            }
    }

    bool diag = (blockIdx.x == blockIdx.y);
    float* s_t = (float*)sm;
    __syncthreads();

#pragma unroll
    for (int mt = 0; mt < 2; mt++)
#pragma unroll
        for (int h = 0; h < 2; h++) {
            int ml = wm * 32 + mt * 16 + h * 8 + (l >> 2);
            int m = M0 + ml;
            float maskm = g_cnt[m] > 0 ? 1.f : 0.f;
            float* gp = G + (size_t)m * NN + N0 + wn * 64 + 2 * (l & 3);
            int nbase = wn * 64 + 2 * (l & 3);
#pragma unroll
            for (int nt = 0; nt < 8; nt++) {
                float s0  = sigf(acc[mt][nt][h * 2 + 0]);
                float s1v = sigf(acc[mt][nt][h * 2 + 1]);
                int nl = nbase + nt * 8;
                if (!diag) {
                    s_t[ml * 128 + ((nl)     ^ (ml & 31))] = s0;
                    s_t[ml * 128 + ((nl + 1) ^ (ml & 31))] = s1v;
                }
                float2 o; o.x = maskm * s0; o.y = maskm * s1v;
                *(float2*)(gp + nt * 8) = o;
            }
        }

    if (diag) return;
    __syncthreads();

    for (int i = tid; i < 128 * 128; i += 256) {
        int nl = i >> 7, ml = i & 127;
        int n = N0 + nl;
        float maskn = g_cnt[n] > 0 ? 1.f : 0.f;
        float v = s_t[ml * 128 + (nl ^ (ml & 31))];
        G[(size_t)n * NN + M0 + ml] = maskn * v;
    }
}

// ---------------- launch ----------------
extern "C" void kernel_launch(void* const* d_in, const int* in_sizes, int n_in,
                              void* d_out, int out_size) {
    const float* X   = (const float*)d_in[0];
    const float* adj = (const float*)d_in[1];
    const float* W1  = (const float*)d_in[2];
    const float* a1  = (const float*)d_in[3];
    const float* W2  = (const float*)d_in[4];
    const float* a2  = (const float*)d_in[5];

    float* out = (float*)d_out;
    float* h2  = out;                                  // [NN, DO]
    float* gen = out + (size_t)NN * DO;                // [NN, NN]
    float* att = gen + (size_t)NN * NN;                // [NN, NN]

    static int inited = 0;
    if (!inited) {
        cudaFuncSetAttribute(k_dec, cudaFuncAttributeMaxDynamicSharedMemorySize, 65536);
        inited = 1;
    }

    k_init<<<1, 128>>>();
    k_wh1<<<NN / 8, 64>>>(X, W1, a1);
    k_att1<<<NN, 256>>>(adj, att);
    k_wh2<<<NN / 8, 32>>>(W2, a2);
    k_att2<<<NN, 128>>>(h2);

    dim3 gdim(NN / 128, NN / 128);
    k_dec<<<gdim, 256, 65536>>>(gen);
}